// round 10
// baseline (speedup 1.0000x reference)
#include <cuda_runtime.h>

// SVDHead: batched Kabsch rotation, SINGLE fused kernel.
//   Per block (one batch): 256 threads reduce H = src^T diag(mask) tgt with
//   fully vectorized float4 loads; thread 0 then runs a branchless MUFU-fast
//   one-sided Jacobi 3x3 SVD (3 sweeps, ~900 cycles) and writes
//   R = V diag(1,1,sgn) U^T (sign on the smallest singular pair,
//   sgn = sign(det H)).
//
//   R9: regs=64 exactly -> 4 CTAs x 256 thr x 64 regs = full 64K-reg RF.
//   __launch_bounds__(256,4) raises residency 3->4 CTAs/SM (24->32 warps) for
//   more loads in flight and better wave-transition/SVD-tail coverage.
//
// B=4096, N=2048.

#define BB 4096
#define NN 2048
#define THREADS 256

__global__ __launch_bounds__(THREADS, 4)
void svdhead_fused_kernel(const float* __restrict__ src,
                          const float* __restrict__ tgt,
                          const float* __restrict__ mask_tgt,
                          float* __restrict__ out)
{
    const int b    = blockIdx.x;
    const int tid  = threadIdx.x;
    const int lane = tid & 31;
    const int warp = tid >> 5;

    float h[9];
    #pragma unroll
    for (int i = 0; i < 9; ++i) h[i] = 0.f;

    const float4* s4 = reinterpret_cast<const float4*>(src)      + (size_t)b * (NN * 3 / 4);
    const float4* t4 = reinterpret_cast<const float4*>(tgt)      + (size_t)b * (NN * 3 / 4);
    const float4* m4 = reinterpret_cast<const float4*>(mask_tgt) + (size_t)b * (NN / 4);

    // Front-batch ALL loads for both iterations (14 float4 loads in flight)
    const int g0 = tid;             // iteration 0
    const int g1 = tid + THREADS;   // iteration 1

    float4 sa0 = s4[g0 * 3 + 0], sb0 = s4[g0 * 3 + 1], sc0 = s4[g0 * 3 + 2];
    float4 ta0 = t4[g0 * 3 + 0], tb0 = t4[g0 * 3 + 1], tc0 = t4[g0 * 3 + 2];
    float4 m0  = m4[g0];
    float4 sa1 = s4[g1 * 3 + 0], sb1 = s4[g1 * 3 + 1], sc1 = s4[g1 * 3 + 2];
    float4 ta1 = t4[g1 * 3 + 0], tb1 = t4[g1 * 3 + 1], tc1 = t4[g1 * 3 + 2];
    float4 m1  = m4[g1];

    #define ACC_POINT(sx, sy, sz, tx, ty, tz, mm)                                              \
        {                                                                                      \
            float w0 = (mm) * (tx), w1 = (mm) * (ty), w2 = (mm) * (tz);                        \
            h[0] = fmaf((sx), w0, h[0]); h[1] = fmaf((sx), w1, h[1]); h[2] = fmaf((sx), w2, h[2]); \
            h[3] = fmaf((sy), w0, h[3]); h[4] = fmaf((sy), w1, h[4]); h[5] = fmaf((sy), w2, h[5]); \
            h[6] = fmaf((sz), w0, h[6]); h[7] = fmaf((sz), w1, h[7]); h[8] = fmaf((sz), w2, h[8]); \
        }

    ACC_POINT(sa0.x, sa0.y, sa0.z, ta0.x, ta0.y, ta0.z, m0.x)
    ACC_POINT(sa0.w, sb0.x, sb0.y, ta0.w, tb0.x, tb0.y, m0.y)
    ACC_POINT(sb0.z, sb0.w, sc0.x, tb0.z, tb0.w, tc0.x, m0.z)
    ACC_POINT(sc0.y, sc0.z, sc0.w, tc0.y, tc0.z, tc0.w, m0.w)

    ACC_POINT(sa1.x, sa1.y, sa1.z, ta1.x, ta1.y, ta1.z, m1.x)
    ACC_POINT(sa1.w, sb1.x, sb1.y, ta1.w, tb1.x, tb1.y, m1.y)
    ACC_POINT(sb1.z, sb1.w, sc1.x, tb1.z, tb1.w, tc1.x, m1.z)
    ACC_POINT(sc1.y, sc1.z, sc1.w, tc1.y, tc1.z, tc1.w, m1.w)

    #undef ACC_POINT

    // warp reduce
    #pragma unroll
    for (int i = 0; i < 9; ++i) {
        #pragma unroll
        for (int off = 16; off > 0; off >>= 1)
            h[i] += __shfl_down_sync(0xffffffffu, h[i], off);
    }

    __shared__ float red[THREADS / 32][9];
    if (lane == 0) {
        #pragma unroll
        for (int i = 0; i < 9; ++i) red[warp][i] = h[i];
    }
    __syncthreads();

    // cross-warp reduce inside warp 0 (threads 0..8 own one H element each),
    // then thread 0 runs the SVD. Other warps exit; their memory work is done.
    if (warp == 0) {
        float hv = 0.f;
        if (lane < 9) {
            #pragma unroll
            for (int w = 0; w < THREADS / 32; ++w) hv += red[w][lane];
            red[0][lane] = hv;
        }
        __syncwarp();

        if (lane == 0) {
            float A[3][3], V[3][3];
            #pragma unroll
            for (int r = 0; r < 3; ++r)
                #pragma unroll
                for (int c = 0; c < 3; ++c) {
                    A[r][c] = red[0][r * 3 + c];
                    V[r][c] = (r == c) ? 1.f : 0.f;
                }

            const float det =
                  A[0][0] * (A[1][1] * A[2][2] - A[1][2] * A[2][1])
                - A[0][1] * (A[1][0] * A[2][2] - A[1][2] * A[2][0])
                + A[0][2] * (A[1][0] * A[2][1] - A[1][1] * A[2][0]);

            // one-sided Jacobi, 3 sweeps, fully unrolled, branchless, MUFU-fast.
            #pragma unroll
            for (int sweep = 0; sweep < 3; ++sweep) {
                #pragma unroll
                for (int pq = 0; pq < 3; ++pq) {
                    const int p = (pq == 2) ? 1 : 0;
                    const int q = (pq == 0) ? 1 : 2;
                    float ap0 = A[0][p], ap1 = A[1][p], ap2 = A[2][p];
                    float aq0 = A[0][q], aq1 = A[1][q], aq2 = A[2][q];
                    float alpha = ap0 * ap0 + ap1 * ap1 + ap2 * ap2;
                    float beta  = aq0 * aq0 + aq1 * aq1 + aq2 * aq2;
                    float gamma = ap0 * aq0 + ap1 * aq1 + ap2 * aq2;
                    float gden  = copysignf(fmaxf(fabsf(gamma), 1e-30f), gamma);
                    float zeta  = __fdividef(beta - alpha, 2.f * gden);  // MUFU.RCP
                    float w     = fmaf(zeta, zeta, 1.f);
                    float sqw   = w * rsqrtf(w);                         // MUFU.RSQ
                    float t     = __fdividef(copysignf(1.f, zeta), fabsf(zeta) + sqw);
                    float c     = rsqrtf(fmaf(t, t, 1.f));               // MUFU.RSQ
                    float s     = c * t;
                    #pragma unroll
                    for (int r = 0; r < 3; ++r) {
                        float xp = A[r][p], xq = A[r][q];
                        A[r][p] = c * xp - s * xq;
                        A[r][q] = s * xp + c * xq;
                        float vp = V[r][p], vq = V[r][q];
                        V[r][p] = c * vp - s * vq;
                        V[r][q] = s * vp + c * vq;
                    }
                }
            }

            // singular values = column norms; U columns = normalized A columns
            float U[3][3], sv[3];
            #pragma unroll
            for (int j = 0; j < 3; ++j) {
                float d = A[0][j] * A[0][j] + A[1][j] * A[1][j] + A[2][j] * A[2][j];
                sv[j] = d;
                float inv = rsqrtf(fmaxf(d, 1e-30f));
                U[0][j] = A[0][j] * inv;
                U[1][j] = A[1][j] * inv;
                U[2][j] = A[2][j] * inv;
            }
            int jmin = 0;
            if (sv[1] < sv[jmin]) jmin = 1;
            if (sv[2] < sv[jmin]) jmin = 2;

            const float sgn = (det < 0.f) ? -1.f : 1.f;
            float coef[3] = {1.f, 1.f, 1.f};
            coef[jmin] = sgn;

            // R = V diag(coef) U^T
            float* o = out + (size_t)b * 9;
            #pragma unroll
            for (int i = 0; i < 3; ++i)
                #pragma unroll
                for (int k = 0; k < 3; ++k) {
                    float acc = coef[0] * V[i][0] * U[k][0]
                              + coef[1] * V[i][1] * U[k][1]
                              + coef[2] * V[i][2] * U[k][2];
                    o[i * 3 + k] = acc;
                }
        }
    }
}

extern "C" void kernel_launch(void* const* d_in, const int* in_sizes, int n_in,
                              void* d_out, int out_size)
{
    const float* src      = (const float*)d_in[0];  // src_pts3d  [B,N,3]
    const float* tgt      = (const float*)d_in[1];  // tgt_pts3d  [B,N,3]
    // d_in[2] = kpt_src_mask — unused by the reference einsum
    const float* mask_tgt = (const float*)d_in[3];  // kpt_tgt_mask [B,N]
    float* out = (float*)d_out;

    svdhead_fused_kernel<<<BB, THREADS>>>(src, tgt, mask_tgt, out);
}

// round 11
// speedup vs baseline: 1.0067x; 1.0067x over previous
#include <cuda_runtime.h>

// SVDHead: batched Kabsch rotation, SINGLE fused PERSISTENT kernel.
//   Grid = 148 SMs x 3 CTAs = 444 blocks; each block loops over ~9 batches.
//   Per batch: 256 threads reduce H = src^T diag(mask) tgt (14 front-batched
//   float4 loads per thread); warp 0 finishes the reduce and thread 0 runs a
//   branchless MUFU-fast one-sided Jacobi 3x3 SVD (3 sweeps) writing
//   R = V diag(1,1,sgn) U^T (sign on smallest singular pair, sgn = sign(det H)).
//   Double-buffered smem reduction lets warps 1-7 start the NEXT batch's loads
//   while warp 0 does the SVD -> tail fully hidden; no wave transitions.
//
//   R10 lesson: forcing 4 CTAs/SM squeezed regs to 63 and broke load batching
//   (DRAM 79%->68%). Stay at (256,3) / 64 regs.
//
// B=4096, N=2048.

#define BB 4096
#define NN 2048
#define THREADS 256
#define GRID 444   // 148 SMs * 3 resident CTAs

__global__ __launch_bounds__(THREADS, 3)
void svdhead_fused_kernel(const float* __restrict__ src,
                          const float* __restrict__ tgt,
                          const float* __restrict__ mask_tgt,
                          float* __restrict__ out)
{
    const int tid  = threadIdx.x;
    const int lane = tid & 31;
    const int warp = tid >> 5;

    __shared__ float red[2][THREADS / 32][9];

    int it = 0;
    for (int b = blockIdx.x; b < BB; b += GRID, ++it) {
        const int buf = it & 1;

        float h[9];
        #pragma unroll
        for (int i = 0; i < 9; ++i) h[i] = 0.f;

        const float4* s4 = reinterpret_cast<const float4*>(src)      + (size_t)b * (NN * 3 / 4);
        const float4* t4 = reinterpret_cast<const float4*>(tgt)      + (size_t)b * (NN * 3 / 4);
        const float4* m4 = reinterpret_cast<const float4*>(mask_tgt) + (size_t)b * (NN / 4);

        // Front-batch ALL loads for both halves (14 float4 loads in flight)
        const int g0 = tid;             // half 0
        const int g1 = tid + THREADS;   // half 1

        float4 sa0 = s4[g0 * 3 + 0], sb0 = s4[g0 * 3 + 1], sc0 = s4[g0 * 3 + 2];
        float4 ta0 = t4[g0 * 3 + 0], tb0 = t4[g0 * 3 + 1], tc0 = t4[g0 * 3 + 2];
        float4 m0  = m4[g0];
        float4 sa1 = s4[g1 * 3 + 0], sb1 = s4[g1 * 3 + 1], sc1 = s4[g1 * 3 + 2];
        float4 ta1 = t4[g1 * 3 + 0], tb1 = t4[g1 * 3 + 1], tc1 = t4[g1 * 3 + 2];
        float4 m1  = m4[g1];

        #define ACC_POINT(sx, sy, sz, tx, ty, tz, mm)                                              \
            {                                                                                      \
                float w0 = (mm) * (tx), w1 = (mm) * (ty), w2 = (mm) * (tz);                        \
                h[0] = fmaf((sx), w0, h[0]); h[1] = fmaf((sx), w1, h[1]); h[2] = fmaf((sx), w2, h[2]); \
                h[3] = fmaf((sy), w0, h[3]); h[4] = fmaf((sy), w1, h[4]); h[5] = fmaf((sy), w2, h[5]); \
                h[6] = fmaf((sz), w0, h[6]); h[7] = fmaf((sz), w1, h[7]); h[8] = fmaf((sz), w2, h[8]); \
            }

        ACC_POINT(sa0.x, sa0.y, sa0.z, ta0.x, ta0.y, ta0.z, m0.x)
        ACC_POINT(sa0.w, sb0.x, sb0.y, ta0.w, tb0.x, tb0.y, m0.y)
        ACC_POINT(sb0.z, sb0.w, sc0.x, tb0.z, tb0.w, tc0.x, m0.z)
        ACC_POINT(sc0.y, sc0.z, sc0.w, tc0.y, tc0.z, tc0.w, m0.w)

        ACC_POINT(sa1.x, sa1.y, sa1.z, ta1.x, ta1.y, ta1.z, m1.x)
        ACC_POINT(sa1.w, sb1.x, sb1.y, ta1.w, tb1.x, tb1.y, m1.y)
        ACC_POINT(sb1.z, sb1.w, sc1.x, tb1.z, tb1.w, tc1.x, m1.z)
        ACC_POINT(sc1.y, sc1.z, sc1.w, tc1.y, tc1.z, tc1.w, m1.w)

        #undef ACC_POINT

        // warp reduce
        #pragma unroll
        for (int i = 0; i < 9; ++i) {
            #pragma unroll
            for (int off = 16; off > 0; off >>= 1)
                h[i] += __shfl_down_sync(0xffffffffu, h[i], off);
        }

        if (lane == 0) {
            #pragma unroll
            for (int i = 0; i < 9; ++i) red[buf][warp][i] = h[i];
        }
        __syncthreads();

        // Warps 1-7 loop around to the next batch's loads immediately (they
        // write red[buf^1] next, so warp 0's read of red[buf] is race-free).
        if (warp == 0) {
            float hv = 0.f;
            if (lane < 9) {
                #pragma unroll
                for (int w = 0; w < THREADS / 32; ++w) hv += red[buf][w][lane];
            }
            // broadcast via shuffle: thread 0 gathers the 9 sums
            if (lane == 0) {
                float A[3][3], V[3][3];
                // hv holds element 0; fetch 1..8 from lanes 1..8 below
                A[0][0] = hv;
                // (filled via shfl after this block — see gather below)
                // placeholder, real gather:
                (void)A; (void)V;
            }
            // gather all 9 into thread 0 via shuffles
            float e0 = __shfl_sync(0x1ffu, hv, 0, 32);
            float e1 = __shfl_sync(0x1ffu, hv, 1, 32);
            float e2 = __shfl_sync(0x1ffu, hv, 2, 32);
            float e3 = __shfl_sync(0x1ffu, hv, 3, 32);
            float e4 = __shfl_sync(0x1ffu, hv, 4, 32);
            float e5 = __shfl_sync(0x1ffu, hv, 5, 32);
            float e6 = __shfl_sync(0x1ffu, hv, 6, 32);
            float e7 = __shfl_sync(0x1ffu, hv, 7, 32);
            float e8 = __shfl_sync(0x1ffu, hv, 8, 32);

            if (lane == 0) {
                float A[3][3], V[3][3];
                A[0][0] = e0; A[0][1] = e1; A[0][2] = e2;
                A[1][0] = e3; A[1][1] = e4; A[1][2] = e5;
                A[2][0] = e6; A[2][1] = e7; A[2][2] = e8;
                #pragma unroll
                for (int r = 0; r < 3; ++r)
                    #pragma unroll
                    for (int c = 0; c < 3; ++c)
                        V[r][c] = (r == c) ? 1.f : 0.f;

                const float det =
                      A[0][0] * (A[1][1] * A[2][2] - A[1][2] * A[2][1])
                    - A[0][1] * (A[1][0] * A[2][2] - A[1][2] * A[2][0])
                    + A[0][2] * (A[1][0] * A[2][1] - A[1][1] * A[2][0]);

                // one-sided Jacobi, 3 sweeps, fully unrolled, branchless, MUFU-fast.
                #pragma unroll
                for (int sweep = 0; sweep < 3; ++sweep) {
                    #pragma unroll
                    for (int pq = 0; pq < 3; ++pq) {
                        const int p = (pq == 2) ? 1 : 0;
                        const int q = (pq == 0) ? 1 : 2;
                        float ap0 = A[0][p], ap1 = A[1][p], ap2 = A[2][p];
                        float aq0 = A[0][q], aq1 = A[1][q], aq2 = A[2][q];
                        float alpha = ap0 * ap0 + ap1 * ap1 + ap2 * ap2;
                        float beta  = aq0 * aq0 + aq1 * aq1 + aq2 * aq2;
                        float gamma = ap0 * aq0 + ap1 * aq1 + ap2 * aq2;
                        float gden  = copysignf(fmaxf(fabsf(gamma), 1e-30f), gamma);
                        float zeta  = __fdividef(beta - alpha, 2.f * gden);  // MUFU.RCP
                        float w     = fmaf(zeta, zeta, 1.f);
                        float sqw   = w * rsqrtf(w);                         // MUFU.RSQ
                        float t     = __fdividef(copysignf(1.f, zeta), fabsf(zeta) + sqw);
                        float c     = rsqrtf(fmaf(t, t, 1.f));               // MUFU.RSQ
                        float s     = c * t;
                        #pragma unroll
                        for (int r = 0; r < 3; ++r) {
                            float xp = A[r][p], xq = A[r][q];
                            A[r][p] = c * xp - s * xq;
                            A[r][q] = s * xp + c * xq;
                            float vp = V[r][p], vq = V[r][q];
                            V[r][p] = c * vp - s * vq;
                            V[r][q] = s * vp + c * vq;
                        }
                    }
                }

                // singular values = column norms; U columns = normalized A columns
                float U[3][3], sv[3];
                #pragma unroll
                for (int j = 0; j < 3; ++j) {
                    float d = A[0][j] * A[0][j] + A[1][j] * A[1][j] + A[2][j] * A[2][j];
                    sv[j] = d;
                    float inv = rsqrtf(fmaxf(d, 1e-30f));
                    U[0][j] = A[0][j] * inv;
                    U[1][j] = A[1][j] * inv;
                    U[2][j] = A[2][j] * inv;
                }
                int jmin = 0;
                if (sv[1] < sv[jmin]) jmin = 1;
                if (sv[2] < sv[jmin]) jmin = 2;

                const float sgn = (det < 0.f) ? -1.f : 1.f;
                float coef[3] = {1.f, 1.f, 1.f};
                coef[jmin] = sgn;

                // R = V diag(coef) U^T
                float* o = out + (size_t)b * 9;
                #pragma unroll
                for (int i = 0; i < 3; ++i)
                    #pragma unroll
                    for (int k = 0; k < 3; ++k) {
                        float acc = coef[0] * V[i][0] * U[k][0]
                                  + coef[1] * V[i][1] * U[k][1]
                                  + coef[2] * V[i][2] * U[k][2];
                        o[i * 3 + k] = acc;
                    }
            }
        }
    }
}

extern "C" void kernel_launch(void* const* d_in, const int* in_sizes, int n_in,
                              void* d_out, int out_size)
{
    const float* src      = (const float*)d_in[0];  // src_pts3d  [B,N,3]
    const float* tgt      = (const float*)d_in[1];  // tgt_pts3d  [B,N,3]
    // d_in[2] = kpt_src_mask — unused by the reference einsum
    const float* mask_tgt = (const float*)d_in[3];  // kpt_tgt_mask [B,N]
    float* out = (float*)d_out;

    svdhead_fused_kernel<<<GRID, THREADS>>>(src, tgt, mask_tgt, out);
}

// round 12
// speedup vs baseline: 1.1166x; 1.1092x over previous
#include <cuda_runtime.h>

// SVDHead: batched Kabsch rotation, SINGLE fused kernel (R9 config — best).
//   Per block (one batch): 256 threads reduce H = src^T diag(mask) tgt with
//   14 front-batched float4 loads per thread; warp 0 finishes the reduce and
//   thread 0 runs a branchless MUFU-fast one-sided Jacobi 3x3 SVD (3 sweeps),
//   writing R = V diag(1,1,sgn) U^T (sign on the smallest singular pair,
//   sgn = sign(det H)).
//
//   R10/R11 lessons: 4 CTAs/SM (63 regs) and persistent blocks (80 regs) both
//   broke the 64-reg/3-CTA/14-load batching equilibrium -> DRAM% fell. Keep
//   grid=4096, __launch_bounds__(256,3).
//   R12 change: __ldcs/__stcs streaming cache hints (data is touched exactly
//   once; evict-first reduces L2 retention pressure). No reg/addressing change.
//
// B=4096, N=2048.

#define BB 4096
#define NN 2048
#define THREADS 256

__global__ __launch_bounds__(THREADS, 3)
void svdhead_fused_kernel(const float* __restrict__ src,
                          const float* __restrict__ tgt,
                          const float* __restrict__ mask_tgt,
                          float* __restrict__ out)
{
    const int b    = blockIdx.x;
    const int tid  = threadIdx.x;
    const int lane = tid & 31;
    const int warp = tid >> 5;

    float h[9];
    #pragma unroll
    for (int i = 0; i < 9; ++i) h[i] = 0.f;

    const float4* s4 = reinterpret_cast<const float4*>(src)      + (size_t)b * (NN * 3 / 4);
    const float4* t4 = reinterpret_cast<const float4*>(tgt)      + (size_t)b * (NN * 3 / 4);
    const float4* m4 = reinterpret_cast<const float4*>(mask_tgt) + (size_t)b * (NN / 4);

    // Front-batch ALL loads for both halves (14 float4 streaming loads in flight)
    const int g0 = tid;             // half 0
    const int g1 = tid + THREADS;   // half 1

    float4 sa0 = __ldcs(&s4[g0 * 3 + 0]);
    float4 sb0 = __ldcs(&s4[g0 * 3 + 1]);
    float4 sc0 = __ldcs(&s4[g0 * 3 + 2]);
    float4 ta0 = __ldcs(&t4[g0 * 3 + 0]);
    float4 tb0 = __ldcs(&t4[g0 * 3 + 1]);
    float4 tc0 = __ldcs(&t4[g0 * 3 + 2]);
    float4 m0  = __ldcs(&m4[g0]);
    float4 sa1 = __ldcs(&s4[g1 * 3 + 0]);
    float4 sb1 = __ldcs(&s4[g1 * 3 + 1]);
    float4 sc1 = __ldcs(&s4[g1 * 3 + 2]);
    float4 ta1 = __ldcs(&t4[g1 * 3 + 0]);
    float4 tb1 = __ldcs(&t4[g1 * 3 + 1]);
    float4 tc1 = __ldcs(&t4[g1 * 3 + 2]);
    float4 m1  = __ldcs(&m4[g1]);

    #define ACC_POINT(sx, sy, sz, tx, ty, tz, mm)                                              \
        {                                                                                      \
            float w0 = (mm) * (tx), w1 = (mm) * (ty), w2 = (mm) * (tz);                        \
            h[0] = fmaf((sx), w0, h[0]); h[1] = fmaf((sx), w1, h[1]); h[2] = fmaf((sx), w2, h[2]); \
            h[3] = fmaf((sy), w0, h[3]); h[4] = fmaf((sy), w1, h[4]); h[5] = fmaf((sy), w2, h[5]); \
            h[6] = fmaf((sz), w0, h[6]); h[7] = fmaf((sz), w1, h[7]); h[8] = fmaf((sz), w2, h[8]); \
        }

    ACC_POINT(sa0.x, sa0.y, sa0.z, ta0.x, ta0.y, ta0.z, m0.x)
    ACC_POINT(sa0.w, sb0.x, sb0.y, ta0.w, tb0.x, tb0.y, m0.y)
    ACC_POINT(sb0.z, sb0.w, sc0.x, tb0.z, tb0.w, tc0.x, m0.z)
    ACC_POINT(sc0.y, sc0.z, sc0.w, tc0.y, tc0.z, tc0.w, m0.w)

    ACC_POINT(sa1.x, sa1.y, sa1.z, ta1.x, ta1.y, ta1.z, m1.x)
    ACC_POINT(sa1.w, sb1.x, sb1.y, ta1.w, tb1.x, tb1.y, m1.y)
    ACC_POINT(sb1.z, sb1.w, sc1.x, tb1.z, tb1.w, tc1.x, m1.z)
    ACC_POINT(sc1.y, sc1.z, sc1.w, tc1.y, tc1.z, tc1.w, m1.w)

    #undef ACC_POINT

    // warp reduce
    #pragma unroll
    for (int i = 0; i < 9; ++i) {
        #pragma unroll
        for (int off = 16; off > 0; off >>= 1)
            h[i] += __shfl_down_sync(0xffffffffu, h[i], off);
    }

    __shared__ float red[THREADS / 32][9];
    if (lane == 0) {
        #pragma unroll
        for (int i = 0; i < 9; ++i) red[warp][i] = h[i];
    }
    __syncthreads();

    // cross-warp reduce inside warp 0 (threads 0..8 own one H element each),
    // then thread 0 runs the SVD. Other warps exit; their memory work is done.
    if (warp == 0) {
        float hv = 0.f;
        if (lane < 9) {
            #pragma unroll
            for (int w = 0; w < THREADS / 32; ++w) hv += red[w][lane];
            red[0][lane] = hv;
        }
        __syncwarp();

        if (lane == 0) {
            float A[3][3], V[3][3];
            #pragma unroll
            for (int r = 0; r < 3; ++r)
                #pragma unroll
                for (int c = 0; c < 3; ++c) {
                    A[r][c] = red[0][r * 3 + c];
                    V[r][c] = (r == c) ? 1.f : 0.f;
                }

            const float det =
                  A[0][0] * (A[1][1] * A[2][2] - A[1][2] * A[2][1])
                - A[0][1] * (A[1][0] * A[2][2] - A[1][2] * A[2][0])
                + A[0][2] * (A[1][0] * A[2][1] - A[1][1] * A[2][0]);

            // one-sided Jacobi, 3 sweeps, fully unrolled, branchless, MUFU-fast.
            #pragma unroll
            for (int sweep = 0; sweep < 3; ++sweep) {
                #pragma unroll
                for (int pq = 0; pq < 3; ++pq) {
                    const int p = (pq == 2) ? 1 : 0;
                    const int q = (pq == 0) ? 1 : 2;
                    float ap0 = A[0][p], ap1 = A[1][p], ap2 = A[2][p];
                    float aq0 = A[0][q], aq1 = A[1][q], aq2 = A[2][q];
                    float alpha = ap0 * ap0 + ap1 * ap1 + ap2 * ap2;
                    float beta  = aq0 * aq0 + aq1 * aq1 + aq2 * aq2;
                    float gamma = ap0 * aq0 + ap1 * aq1 + ap2 * aq2;
                    float gden  = copysignf(fmaxf(fabsf(gamma), 1e-30f), gamma);
                    float zeta  = __fdividef(beta - alpha, 2.f * gden);  // MUFU.RCP
                    float w     = fmaf(zeta, zeta, 1.f);
                    float sqw   = w * rsqrtf(w);                         // MUFU.RSQ
                    float t     = __fdividef(copysignf(1.f, zeta), fabsf(zeta) + sqw);
                    float c     = rsqrtf(fmaf(t, t, 1.f));               // MUFU.RSQ
                    float s     = c * t;
                    #pragma unroll
                    for (int r = 0; r < 3; ++r) {
                        float xp = A[r][p], xq = A[r][q];
                        A[r][p] = c * xp - s * xq;
                        A[r][q] = s * xp + c * xq;
                        float vp = V[r][p], vq = V[r][q];
                        V[r][p] = c * vp - s * vq;
                        V[r][q] = s * vp + c * vq;
                    }
                }
            }

            // singular values = column norms; U columns = normalized A columns
            float U[3][3], sv[3];
            #pragma unroll
            for (int j = 0; j < 3; ++j) {
                float d = A[0][j] * A[0][j] + A[1][j] * A[1][j] + A[2][j] * A[2][j];
                sv[j] = d;
                float inv = rsqrtf(fmaxf(d, 1e-30f));
                U[0][j] = A[0][j] * inv;
                U[1][j] = A[1][j] * inv;
                U[2][j] = A[2][j] * inv;
            }
            int jmin = 0;
            if (sv[1] < sv[jmin]) jmin = 1;
            if (sv[2] < sv[jmin]) jmin = 2;

            const float sgn = (det < 0.f) ? -1.f : 1.f;
            float coef[3] = {1.f, 1.f, 1.f};
            coef[jmin] = sgn;

            // R = V diag(coef) U^T — streaming stores
            float* o = out + (size_t)b * 9;
            #pragma unroll
            for (int i = 0; i < 3; ++i)
                #pragma unroll
                for (int k = 0; k < 3; ++k) {
                    float acc = coef[0] * V[i][0] * U[k][0]
                              + coef[1] * V[i][1] * U[k][1]
                              + coef[2] * V[i][2] * U[k][2];
                    __stcs(&o[i * 3 + k], acc);
                }
        }
    }
}

extern "C" void kernel_launch(void* const* d_in, const int* in_sizes, int n_in,
                              void* d_out, int out_size)
{
    const float* src      = (const float*)d_in[0];  // src_pts3d  [B,N,3]
    const float* tgt      = (const float*)d_in[1];  // tgt_pts3d  [B,N,3]
    // d_in[2] = kpt_src_mask — unused by the reference einsum
    const float* mask_tgt = (const float*)d_in[3];  // kpt_tgt_mask [B,N]
    float* out = (float*)d_out;

    svdhead_fused_kernel<<<BB, THREADS>>>(src, tgt, mask_tgt, out);
}